// round 3
// baseline (speedup 1.0000x reference)
#include <cuda_runtime.h>
#include <cstdint>

typedef unsigned long long u64;

// Problem dims (fixed): B=4, N=16384 -> 65536 rows, Dn=128, L=256, H=8, DH=32.
// Only the graph hetero branch (T=1) affects the output (loop overwrites `out`).

#define NROWS_TOTAL 65536
#define ROWS_PER_BLK 64
#define THREADS 256
#define SMEM_BYTES 144384  // 36096 floats

// Packed f32x2 helpers (Blackwell sm_10x)
#define FMA2(d, a, b, c) \
    asm("fma.rn.f32x2 %0, %1, %2, %3;" : "=l"(d) : "l"(a), "l"(b), "l"(c))
#define PACK2(d, lo, hi) \
    asm("mov.b64 %0, {%1, %2};" : "=l"(d) : "r"(__float_as_uint(lo)), "r"(__float_as_uint(hi)))
#define UNPACK2(lo, hi, v) \
    do { unsigned _a, _b; asm("mov.b64 {%0, %1}, %2;" : "=r"(_a), "=r"(_b) : "l"(v)); \
         lo = __uint_as_float(_a); hi = __uint_as_float(_b); } while (0)

// Precomputed small tensors (device globals; no runtime alloc allowed)
__device__ float g_Wnq[128 * 256];  // W_node @ Wq
__device__ float g_bnq[256];        // b_node @ Wq + bq
__device__ float g_kvec[256];       // per-head softmaxed k (graph branch)
__device__ float g_U[8 * 256];      // U[h] = v_h @ W_out[h*32:(h+1)*32, :]
__device__ float g_lg[256];         // lifted graph feature
__device__ float g_kraw[256];       // pre-softmax k
__device__ float g_vraw[256];       // v

// ---------------------------------------------------------------------------
// P1: lifted_graph = energy @ W_graph + b_graph   (K=32, trivial)
// ---------------------------------------------------------------------------
__global__ void p1_kernel(const float* __restrict__ energy,
                          const float* __restrict__ W_graph,
                          const float* __restrict__ b_graph)
{
    const int j = threadIdx.x;
    float acc = b_graph[j];
    #pragma unroll
    for (int d = 0; d < 32; d++) acc += energy[d] * W_graph[d * 256 + j];
    g_lg[j] = acc;
}

// ---------------------------------------------------------------------------
// P2: three K=256 GEMVs, warp-per-output (768 outputs total):
//   out 0..255   : kraw[j] = bk2[j] + lg @ Wk2[:,j]
//   out 256..511 : vraw[j] = bv2[j] + lg @ Wv2[:,j]
//   out 512..767 : bnq[j]  = bq[j]  + b_node @ Wq[:,j]
// ---------------------------------------------------------------------------
__global__ void p2_kernel(const float* __restrict__ Wk, const float* __restrict__ bk,
                          const float* __restrict__ Wv, const float* __restrict__ bv,
                          const float* __restrict__ Wq, const float* __restrict__ bq,
                          const float* __restrict__ b_node)
{
    const int warp = threadIdx.x >> 5, lane = threadIdx.x & 31;
    const int oid = blockIdx.x * 8 + warp;      // 0..767
    const int kind = oid >> 8;                  // 0=k, 1=v, 2=bnq
    const int j = oid & 255;

    const float* W; const float* xv; float bias;
    if (kind == 0)      { W = Wk + 2 * 65536; xv = g_lg;  bias = bk[512 + j]; }
    else if (kind == 1) { W = Wv + 2 * 65536; xv = g_lg;  bias = bv[512 + j]; }
    else                { W = Wq;             xv = b_node; bias = bq[j]; }

    float s = 0.0f;
    #pragma unroll
    for (int u = 0; u < 8; u++) {
        const int i = lane + 32 * u;
        s += xv[i] * W[i * 256 + j];
    }
    #pragma unroll
    for (int o = 16; o > 0; o >>= 1) s += __shfl_xor_sync(0xffffffffu, s, o);
    if (lane == 0) {
        s += bias;
        if (kind == 0) g_kraw[j] = s;
        else if (kind == 1) g_vraw[j] = s;
        else g_bnq[j] = s;
    }
}

// ---------------------------------------------------------------------------
// P3: block 0 -> per-head softmax(kraw); blocks 1..8 -> U[h] = v_h @ W_out_h
// ---------------------------------------------------------------------------
__global__ void p3_kernel(const float* __restrict__ W_out)
{
    const int j = threadIdx.x;
    if (blockIdx.x == 0) {
        const int w = j >> 5, lane = j & 31;
        float x = g_kraw[w * 32 + lane];
        float m = x;
        #pragma unroll
        for (int o = 16; o > 0; o >>= 1) m = fmaxf(m, __shfl_xor_sync(0xffffffffu, m, o));
        const float e = __expf(x - m);
        float s = e;
        #pragma unroll
        for (int o = 16; o > 0; o >>= 1) s += __shfl_xor_sync(0xffffffffu, s, o);
        g_kvec[w * 32 + lane] = e / s;
    } else {
        const int h = blockIdx.x - 1;
        __shared__ float sv[32];
        if (j < 32) sv[j] = g_vraw[h * 32 + j];
        __syncthreads();
        float u = 0.0f;
        #pragma unroll
        for (int e2 = 0; e2 < 32; e2++)
            u += sv[e2] * W_out[(h * 32 + e2) * 256 + j];
        g_U[h * 256 + j] = u;
    }
}

// ---------------------------------------------------------------------------
// P4: Wnq = W_node(128x256) @ Wq(256x256). Block i = output row.
// ---------------------------------------------------------------------------
__global__ void p4_kernel(const float* __restrict__ W_node,
                          const float* __restrict__ Wq)
{
    __shared__ float srow[256];
    const int i = blockIdx.x;   // 0..127
    const int j = threadIdx.x;  // 0..255
    srow[j] = W_node[i * 256 + j];
    __syncthreads();
    float acc = 0.0f;
    for (int m = 0; m < 256; m++) acc += srow[m] * Wq[m * 256 + j];
    g_Wnq[i * 256 + j] = acc;
}

// ---------------------------------------------------------------------------
// Main fused kernel: per 64-row tile
//   Y = X(64x128) @ Wnq + bnq  -> per-head softmax -> q, c
//   Z = q @ W_out + c @ U + b_out
// Thread mapping: tcol = tid&31 (lane), trow = tid>>5 (warp).
// Thread owns rows {trow + 8i} and cols {tcol + 32j}  (i,j in 0..7).
// Accumulators packed f32x2 along row pairs: acc2[p][j] = {row 16p, row 16p+8}.
// ---------------------------------------------------------------------------
extern __shared__ float s_mem[];

__global__ __launch_bounds__(THREADS, 1)
void ghca_main_kernel(const float* __restrict__ X,
                      const float* __restrict__ W_out,
                      const float* __restrict__ b_out,
                      float* __restrict__ out)
{
    float* Xs  = s_mem;          //  8192 floats: X tile  [64][128]
    float* Ws  = Xs + 8192;      //  8192 floats: weight stage [32][256]
    float* Qs  = Ws + 8192;      // 16384 floats: q tile  [64][256]
    float* Us  = Qs + 16384;     //  2048 floats: U       [8][256]
    float* Cs  = Us + 2048;      //   512 floats: c       [64][8]
    float* bb  = Cs + 512;       //   256 floats: b_out
    float* kvs = bb + 256;       //   256 floats: softmaxed k
    float* bnq = kvs + 256;      //   256 floats: fused bias

    const int tid  = threadIdx.x;
    const int row0 = blockIdx.x * ROWS_PER_BLK;
    const int tcol = tid & 31;
    const int trow = tid >> 5;

    // ---- cooperative loads ----
    {
        const float4* src = (const float4*)(X + (size_t)row0 * 128);
        float4* dst = (float4*)Xs;
        #pragma unroll
        for (int t = tid; t < 2048; t += THREADS) dst[t] = src[t];
        const float4* us = (const float4*)g_U;
        float4* ud = (float4*)Us;
        #pragma unroll
        for (int t = tid; t < 512; t += THREADS) ud[t] = us[t];
        bb[tid]  = b_out[tid];
        kvs[tid] = g_kvec[tid];
        bnq[tid] = g_bnq[tid];
    }

    u64 acc2[4][8];
    #pragma unroll
    for (int p = 0; p < 4; p++)
        #pragma unroll
        for (int j = 0; j < 8; j++) acc2[p][j] = 0ULL;

    // ---- Phase 1: Y = X @ Wnq (K = 128, staged 32 rows at a time) ----
    for (int kk = 0; kk < 4; kk++) {
        __syncthreads();
        {
            const float4* wsrc = (const float4*)(g_Wnq + kk * 32 * 256);
            float4* wdst = (float4*)Ws;
            #pragma unroll
            for (int t = tid; t < 2048; t += THREADS) wdst[t] = wsrc[t];
        }
        __syncthreads();
        #pragma unroll
        for (int k2 = 0; k2 < 32; k2++) {
            const int k = kk * 32 + k2;
            u64 a2[4], b2[8];
            #pragma unroll
            for (int p = 0; p < 4; p++) {
                const float alo = Xs[(trow + 16 * p) * 128 + k];
                const float ahi = Xs[(trow + 16 * p + 8) * 128 + k];
                PACK2(a2[p], alo, ahi);
            }
            #pragma unroll
            for (int j = 0; j < 8; j++) {
                const float b = Ws[k2 * 256 + tcol + 32 * j];
                PACK2(b2[j], b, b);
            }
            #pragma unroll
            for (int p = 0; p < 4; p++)
                #pragma unroll
                for (int j = 0; j < 8; j++)
                    FMA2(acc2[p][j], a2[p], b2[j], acc2[p][j]);
        }
    }

    // ---- bias + per-head softmax + c = s/max(s,1e-8) ----
    #pragma unroll
    for (int p = 0; p < 4; p++) {
        #pragma unroll
        for (int half = 0; half < 2; half++) {
            const int row = trow + 16 * p + 8 * half;
            #pragma unroll
            for (int j = 0; j < 8; j++) {
                float ylo, yhi;
                UNPACK2(ylo, yhi, acc2[p][j]);
                const float y = (half ? yhi : ylo) + bnq[tcol + 32 * j];
                float m = y;
                #pragma unroll
                for (int o = 16; o > 0; o >>= 1) m = fmaxf(m, __shfl_xor_sync(0xffffffffu, m, o));
                const float e = __expf(y - m);
                float s = e;
                #pragma unroll
                for (int o = 16; o > 0; o >>= 1) s += __shfl_xor_sync(0xffffffffu, s, o);
                const float q = e / s;
                Qs[row * 256 + tcol + 32 * j] = q;
                float pdot = q * kvs[32 * j + tcol];
                #pragma unroll
                for (int o = 16; o > 0; o >>= 1) pdot += __shfl_xor_sync(0xffffffffu, pdot, o);
                if (tcol == 0) Cs[row * 8 + j] = (pdot >= 1e-8f) ? 1.0f : pdot * 1e8f;
            }
        }
    }

    // ---- Phase 2: Z = Q @ W_out (K = 256) ----
    #pragma unroll
    for (int p = 0; p < 4; p++)
        #pragma unroll
        for (int j = 0; j < 8; j++) acc2[p][j] = 0ULL;

    for (int kk = 0; kk < 8; kk++) {
        __syncthreads();
        {
            const float4* wsrc = (const float4*)(W_out + kk * 32 * 256);
            float4* wdst = (float4*)Ws;
            #pragma unroll
            for (int t = tid; t < 2048; t += THREADS) wdst[t] = wsrc[t];
        }
        __syncthreads();
        #pragma unroll
        for (int k2 = 0; k2 < 32; k2++) {
            const int m = kk * 32 + k2;
            u64 a2[4], b2[8];
            #pragma unroll
            for (int p = 0; p < 4; p++) {
                const float alo = Qs[(trow + 16 * p) * 256 + m];
                const float ahi = Qs[(trow + 16 * p + 8) * 256 + m];
                PACK2(a2[p], alo, ahi);
            }
            #pragma unroll
            for (int j = 0; j < 8; j++) {
                const float b = Ws[k2 * 256 + tcol + 32 * j];
                PACK2(b2[j], b, b);
            }
            #pragma unroll
            for (int p = 0; p < 4; p++)
                #pragma unroll
                for (int j = 0; j < 8; j++)
                    FMA2(acc2[p][j], a2[p], b2[j], acc2[p][j]);
        }
    }

    // ---- epilogue: + c @ U + b_out, write out ----
    #pragma unroll
    for (int p = 0; p < 4; p++) {
        #pragma unroll
        for (int half = 0; half < 2; half++) {
            const int row = trow + 16 * p + 8 * half;
            float c[8];
            #pragma unroll
            for (int h = 0; h < 8; h++) c[h] = Cs[row * 8 + h];
            #pragma unroll
            for (int j = 0; j < 8; j++) {
                const int col = tcol + 32 * j;
                float zlo, zhi;
                UNPACK2(zlo, zhi, acc2[p][j]);
                float r = (half ? zhi : zlo) + bb[col];
                #pragma unroll
                for (int h = 0; h < 8; h++) r = fmaf(c[h], Us[h * 256 + col], r);
                out[(size_t)(row0 + row) * 256 + col] = r;
            }
        }
    }
}

// ---------------------------------------------------------------------------
// Launch. Input order: node_features, edge_features, energy, W_node, b_node,
// W_edge, b_edge, W_graph, b_graph, Wq, bq, Wk, bk, Wv, bv, W_out, b_out.
// edge_features / W_edge / b_edge are dead (loop overwrite in reference).
// ---------------------------------------------------------------------------
extern "C" void kernel_launch(void* const* d_in, const int* in_sizes, int n_in,
                              void* d_out, int out_size)
{
    const float* node    = (const float*)d_in[0];
    const float* energy  = (const float*)d_in[2];
    const float* W_node  = (const float*)d_in[3];
    const float* b_node  = (const float*)d_in[4];
    const float* W_graph = (const float*)d_in[7];
    const float* b_graph = (const float*)d_in[8];
    const float* Wq      = (const float*)d_in[9];
    const float* bq      = (const float*)d_in[10];
    const float* Wk      = (const float*)d_in[11];
    const float* bk      = (const float*)d_in[12];
    const float* Wv      = (const float*)d_in[13];
    const float* bv      = (const float*)d_in[14];
    const float* W_out   = (const float*)d_in[15];
    const float* b_out   = (const float*)d_in[16];
    float* out = (float*)d_out;

    p1_kernel<<<1, 256>>>(energy, W_graph, b_graph);
    p2_kernel<<<96, 256>>>(Wk, bk, Wv, bv, Wq, bq, b_node);
    p3_kernel<<<9, 256>>>(W_out);
    p4_kernel<<<128, 256>>>(W_node, Wq);

    cudaFuncSetAttribute(ghca_main_kernel,
                         cudaFuncAttributeMaxDynamicSharedMemorySize, SMEM_BYTES);
    ghca_main_kernel<<<NROWS_TOTAL / ROWS_PER_BLK, THREADS, SMEM_BYTES>>>(
        node, W_out, b_out, out);
}

// round 5
// speedup vs baseline: 2.9721x; 2.9721x over previous
#include <cuda_runtime.h>
#include <cuda_bf16.h>
#include <cstdint>

typedef uint32_t u32;
typedef uint16_t u16;

// Fixed dims: 65536 rows, Dn=128, L=256, H=8, DH=32. Only graph branch matters
// (reference loop overwrites `out`; graph branch has T=1 -> rank-1 kv).
#define NROWS_TOTAL 65536
#define ROWS_PER_BLK 128
#define THREADS 512
#define NBLKS (NROWS_TOTAL / ROWS_PER_BLK)   // 512

// ---------------- SMEM layout (bytes) --------------------------------------
// small float region f[0..4095]:
//   f[0..255]    bnq       f[256..511]  kvec      f[512..767] b_out
//   f[768..2815] U[8][256] f[2816..3839] c[128][8]
// big region @16384 (208896 B), two overlays:
//  phase1: XH@16384 (34816) XL@51200 WNQH@86016 (69632) WNQL@155648
//  phase2: QH@16384 (67584) QL@83968 WCH@151552 (36864) WCL@188416
#define OFF_XH   16384
#define OFF_XL   51200
#define OFF_WNQH 86016
#define OFF_WNQL 155648
#define OFF_QH   16384
#define OFF_QL   83968
#define OFF_WCH  151552
#define OFF_WCL  188416
#define SMEM_BYTES 225280

// padded strides (in u32 words = bf16 pairs)
#define XSTR 68     // 136 bf16 per row (K=128 + 8 pad)
#define QSTR 132    // 264 bf16 per row (K=256 + 8 pad)
#define WCSTR 36    // 72 bf16 per row  (K=64 chunk + 8 pad)

// ---------------- device globals (precomputed each launch) -----------------
__device__ __nv_bfloat16 g_WnqH[256 * 136];   // (W_node@Wq)^T  [n][k] padded
__device__ __nv_bfloat16 g_WnqL[256 * 136];
__device__ __nv_bfloat16 g_WoutH[256 * 264];  // W_out^T        [n][k] padded
__device__ __nv_bfloat16 g_WoutL[256 * 264];
__device__ float g_bnq[256], g_kvec[256], g_U[2048];
__device__ float g_lg[256], g_kraw[256], g_vraw[256];

// ---------------- mma wrapper ----------------------------------------------
__device__ __forceinline__ void mma16816(float* d, const u32* a, const u32* b) {
    asm volatile(
        "mma.sync.aligned.m16n8k16.row.col.f32.bf16.bf16.f32 "
        "{%0,%1,%2,%3}, {%4,%5,%6,%7}, {%8,%9}, {%0,%1,%2,%3};"
        : "+f"(d[0]), "+f"(d[1]), "+f"(d[2]), "+f"(d[3])
        : "r"(a[0]), "r"(a[1]), "r"(a[2]), "r"(a[3]), "r"(b[0]), "r"(b[1]));
}

__device__ __forceinline__ u32 packbf2(float x, float y) {
    __nv_bfloat162 h = __floats2bfloat162_rn(x, y);
    return ((u32)__bfloat16_as_ushort(h.y) << 16) | (u32)__bfloat16_as_ushort(h.x);
}

// ---------------- precompute kernels ---------------------------------------
__global__ void p1_kernel(const float* __restrict__ energy,
                          const float* __restrict__ W_graph,
                          const float* __restrict__ b_graph)
{
    const int j = threadIdx.x;
    float acc = b_graph[j];
    #pragma unroll
    for (int d = 0; d < 32; d++) acc += energy[d] * W_graph[d * 256 + j];
    g_lg[j] = acc;
}

__global__ void p2_kernel(const float* __restrict__ Wk, const float* __restrict__ bk,
                          const float* __restrict__ Wv, const float* __restrict__ bv,
                          const float* __restrict__ Wq, const float* __restrict__ bq,
                          const float* __restrict__ b_node)
{
    const int warp = threadIdx.x >> 5, lane = threadIdx.x & 31;
    const int oid = blockIdx.x * 8 + warp;
    const int kind = oid >> 8;
    const int j = oid & 255;
    const float* W; const float* xv; float bias;
    if (kind == 0)      { W = Wk + 2 * 65536; xv = g_lg;   bias = bk[512 + j]; }
    else if (kind == 1) { W = Wv + 2 * 65536; xv = g_lg;   bias = bv[512 + j]; }
    else                { W = Wq;             xv = b_node; bias = bq[j]; }
    float s = 0.0f;
    #pragma unroll
    for (int u = 0; u < 8; u++) { int i = lane + 32 * u; s += xv[i] * W[i * 256 + j]; }
    #pragma unroll
    for (int o = 16; o > 0; o >>= 1) s += __shfl_xor_sync(0xffffffffu, s, o);
    if (lane == 0) {
        s += bias;
        if (kind == 0) g_kraw[j] = s;
        else if (kind == 1) g_vraw[j] = s;
        else g_bnq[j] = s;
    }
}

__global__ void p3_kernel(const float* __restrict__ W_out)
{
    const int j = threadIdx.x;
    if (blockIdx.x == 0) {
        const int w = j >> 5, lane = j & 31;
        float x = g_kraw[w * 32 + lane];
        float m = x;
        #pragma unroll
        for (int o = 16; o > 0; o >>= 1) m = fmaxf(m, __shfl_xor_sync(0xffffffffu, m, o));
        const float e = __expf(x - m);
        float s = e;
        #pragma unroll
        for (int o = 16; o > 0; o >>= 1) s += __shfl_xor_sync(0xffffffffu, s, o);
        g_kvec[w * 32 + lane] = e / s;
    } else {
        const int h = blockIdx.x - 1;
        __shared__ float sv[32];
        if (j < 32) sv[j] = g_vraw[h * 32 + j];
        __syncthreads();
        float u = 0.0f;
        #pragma unroll
        for (int e2 = 0; e2 < 32; e2++) u += sv[e2] * W_out[(h * 32 + e2) * 256 + j];
        g_U[h * 256 + j] = u;
    }
}

// p4: Wnq = W_node @ Wq, stored transposed+padded, split hi/lo bf16.
__global__ void p4_kernel(const float* __restrict__ W_node,
                          const float* __restrict__ Wq)
{
    const int i = blockIdx.x;   // k 0..127
    const int j = threadIdx.x;  // n 0..255
    const float* wn = W_node + i * 256;
    float a0 = 0.f, a1 = 0.f, a2 = 0.f, a3 = 0.f;
    #pragma unroll 8
    for (int m = 0; m < 256; m += 4) {
        a0 = fmaf(wn[m],     Wq[m * 256 + j],       a0);
        a1 = fmaf(wn[m + 1], Wq[(m + 1) * 256 + j], a1);
        a2 = fmaf(wn[m + 2], Wq[(m + 2) * 256 + j], a2);
        a3 = fmaf(wn[m + 3], Wq[(m + 3) * 256 + j], a3);
    }
    float acc = (a0 + a1) + (a2 + a3);
    __nv_bfloat16 h = __float2bfloat16(acc);
    __nv_bfloat16 l = __float2bfloat16(acc - __bfloat162float(h));
    g_WnqH[j * 136 + i] = h;
    g_WnqL[j * 136 + i] = l;
}

// p5: W_out transposed+padded split.
__global__ void p5_kernel(const float* __restrict__ W_out)
{
    const int m = blockIdx.x;    // k 0..255
    const int j = threadIdx.x;   // n 0..255
    float w = W_out[m * 256 + j];
    __nv_bfloat16 h = __float2bfloat16(w);
    __nv_bfloat16 l = __float2bfloat16(w - __bfloat162float(h));
    g_WoutH[j * 264 + m] = h;
    g_WoutL[j * 264 + m] = l;
}

// ---------------- main HMMA kernel -----------------------------------------
extern __shared__ char s_raw[];

__global__ __launch_bounds__(THREADS, 1)
void ghca_main_kernel(const float* __restrict__ X,
                      const float* __restrict__ b_out,
                      float* __restrict__ out)
{
    float* f = (float*)s_raw;
    const int tid = threadIdx.x;
    const int wid = tid >> 5, lane = tid & 31;
    const int g = lane >> 2, tig = lane & 3;
    const int wr = wid & 3, wc = wid >> 2;     // warp: rows wr*32.., cols wc*64..
    const int row0 = blockIdx.x * ROWS_PER_BLK;

    // ---- stage small arrays ----
    for (int t = tid; t < 256; t += THREADS) {
        f[t]       = g_bnq[t];
        f[256 + t] = g_kvec[t];
        f[512 + t] = b_out[t];
    }
    for (int t = tid; t < 2048; t += THREADS) f[768 + t] = g_U[t];

    // ---- stage X split (row-major padded) ----
    {
        u32* xh = (u32*)(s_raw + OFF_XH);
        u32* xl = (u32*)(s_raw + OFF_XL);
        const float2* xs = (const float2*)(X + (size_t)row0 * 128);
        #pragma unroll 4
        for (int idx = tid; idx < 8192; idx += THREADS) {
            const int r = idx >> 6, cp = idx & 63;
            float2 v = xs[idx];
            __nv_bfloat162 hh = __floats2bfloat162_rn(v.x, v.y);
            xh[r * XSTR + cp] = ((u32)__bfloat16_as_ushort(hh.y) << 16) |
                                (u32)__bfloat16_as_ushort(hh.x);
            xl[r * XSTR + cp] = packbf2(v.x - __bfloat162float(hh.x),
                                        v.y - __bfloat162float(hh.y));
        }
    }
    // ---- stage Wnq split (linear copy, arrays are already padded) ----
    {
        float4* dh = (float4*)(s_raw + OFF_WNQH);
        float4* dl = (float4*)(s_raw + OFF_WNQL);
        const float4* sh = (const float4*)g_WnqH;
        const float4* sl = (const float4*)g_WnqL;
        #pragma unroll 4
        for (int t = tid; t < 4352; t += THREADS) { dh[t] = sh[t]; dl[t] = sl[t]; }
    }
    __syncthreads();

    float d[2][8][4];
    #pragma unroll
    for (int mt = 0; mt < 2; mt++)
        #pragma unroll
        for (int nt = 0; nt < 8; nt++)
            #pragma unroll
            for (int c = 0; c < 4; c++) d[mt][nt][c] = 0.0f;

    // ---- phase 1: Y = X @ Wnq  (K=128, 8 ksteps) ----
    {
        const u32* Xh = (const u32*)(s_raw + OFF_XH);
        const u32* Xl = (const u32*)(s_raw + OFF_XL);
        const u32* Bh = (const u32*)(s_raw + OFF_WNQH);
        const u32* Bl = (const u32*)(s_raw + OFF_WNQL);
        #pragma unroll
        for (int ks = 0; ks < 8; ks++) {
            u32 ah[2][4], al[2][4];
            #pragma unroll
            for (int mt = 0; mt < 2; mt++) {
                const int base = (wr * 32 + mt * 16 + g) * XSTR + ks * 8 + tig;
                ah[mt][0] = Xh[base];            ah[mt][1] = Xh[base + 8 * XSTR];
                ah[mt][2] = Xh[base + 4];        ah[mt][3] = Xh[base + 8 * XSTR + 4];
                al[mt][0] = Xl[base];            al[mt][1] = Xl[base + 8 * XSTR];
                al[mt][2] = Xl[base + 4];        al[mt][3] = Xl[base + 8 * XSTR + 4];
            }
            #pragma unroll
            for (int nt = 0; nt < 8; nt++) {
                const int nb = (wc * 64 + nt * 8 + g) * XSTR + ks * 8 + tig;
                u32 bh[2] = { Bh[nb], Bh[nb + 4] };
                u32 bl[2] = { Bl[nb], Bl[nb + 4] };
                #pragma unroll
                for (int mt = 0; mt < 2; mt++) {
                    mma16816(d[mt][nt], ah[mt], bh);
                    mma16816(d[mt][nt], ah[mt], bl);
                    mma16816(d[mt][nt], al[mt], bh);
                }
            }
        }
    }
    __syncthreads();   // phase1 SMEM reads done; safe to overwrite with Q

    // ---- softmax per row per head, build c, write Q split to SMEM ----
    {
        u32* Qh = (u32*)(s_raw + OFF_QH);
        u32* Ql = (u32*)(s_raw + OFF_QL);
        float* fc = f + 2816;
        #pragma unroll
        for (int mt = 0; mt < 2; mt++) {
            #pragma unroll
            for (int rh = 0; rh < 2; rh++) {
                const int row = wr * 32 + mt * 16 + rh * 8 + g;
                #pragma unroll
                for (int hg = 0; hg < 2; hg++) {
                    const int head = wc * 2 + hg;
                    float y[8];
                    #pragma unroll
                    for (int q = 0; q < 4; q++) {
                        const int col = wc * 64 + (hg * 4 + q) * 8 + tig * 2;
                        y[q * 2]     = d[mt][hg * 4 + q][rh * 2]     + f[col];
                        y[q * 2 + 1] = d[mt][hg * 4 + q][rh * 2 + 1] + f[col + 1];
                    }
                    float mx = y[0];
                    #pragma unroll
                    for (int q = 1; q < 8; q++) mx = fmaxf(mx, y[q]);
                    mx = fmaxf(mx, __shfl_xor_sync(0xffffffffu, mx, 1));
                    mx = fmaxf(mx, __shfl_xor_sync(0xffffffffu, mx, 2));
                    float s = 0.0f;
                    #pragma unroll
                    for (int q = 0; q < 8; q++) { y[q] = __expf(y[q] - mx); s += y[q]; }
                    s += __shfl_xor_sync(0xffffffffu, s, 1);
                    s += __shfl_xor_sync(0xffffffffu, s, 2);
                    const float inv = 1.0f / s;
                    float pd = 0.0f;
                    #pragma unroll
                    for (int q = 0; q < 4; q++) {
                        const int col = wc * 64 + (hg * 4 + q) * 8 + tig * 2;
                        y[q * 2]     *= inv;
                        y[q * 2 + 1] *= inv;
                        pd += y[q * 2] * f[256 + col] + y[q * 2 + 1] * f[256 + col + 1];
                    }
                    pd += __shfl_xor_sync(0xffffffffu, pd, 1);
                    pd += __shfl_xor_sync(0xffffffffu, pd, 2);
                    if (tig == 0)
                        fc[row * 8 + head] = (pd >= 1e-8f) ? 1.0f : pd * 1e8f;
                    #pragma unroll
                    for (int q = 0; q < 4; q++) {
                        const int wi = row * QSTR + wc * 32 + (hg * 4 + q) * 4 + tig;
                        const float q0 = y[q * 2], q1 = y[q * 2 + 1];
                        __nv_bfloat162 hh = __floats2bfloat162_rn(q0, q1);
                        Qh[wi] = ((u32)__bfloat16_as_ushort(hh.y) << 16) |
                                 (u32)__bfloat16_as_ushort(hh.x);
                        Ql[wi] = packbf2(q0 - __bfloat162float(hh.x),
                                         q1 - __bfloat162float(hh.y));
                    }
                }
            }
        }
    }

    // ---- phase 2: Z = Q @ W_out  (K=256, 4 staged chunks of 64) ----
    #pragma unroll
    for (int mt = 0; mt < 2; mt++)
        #pragma unroll
        for (int nt = 0; nt < 8; nt++)
            #pragma unroll
            for (int c = 0; c < 4; c++) d[mt][nt][c] = 0.0f;

    for (int ck = 0; ck < 4; ck++) {
        __syncthreads();   // previous chunk's reads (or Q writes) complete
        {
            float4* dh = (float4*)(s_raw + OFF_WCH);
            float4* dl = (float4*)(s_raw + OFF_WCL);
            const float4* sh = (const float4*)g_WoutH;
            const float4* sl = (const float4*)g_WoutL;
            #pragma unroll
            for (int t = tid; t < 2048; t += THREADS) {
                const int r = t >> 3, seg = t & 7;
                const int si = r * 33 + ck * 8 + seg;   // 264 bf16 = 33 float4
                const int di = r * 9 + seg;             // 72 bf16 = 9 float4
                dh[di] = sh[si];
                dl[di] = sl[si];
            }
        }
        __syncthreads();
        const u32* Qh = (const u32*)(s_raw + OFF_QH);
        const u32* Ql = (const u32*)(s_raw + OFF_QL);
        const u32* Bh = (const u32*)(s_raw + OFF_WCH);
        const u32* Bl = (const u32*)(s_raw + OFF_WCL);
        #pragma unroll
        for (int ks = 0; ks < 4; ks++) {
            u32 ah[2][4], al[2][4];
            #pragma unroll
            for (int mt = 0; mt < 2; mt++) {
                const int base = (wr * 32 + mt * 16 + g) * QSTR + ck * 32 + ks * 8 + tig;
                ah[mt][0] = Qh[base];        ah[mt][1] = Qh[base + 8 * QSTR];
                ah[mt][2] = Qh[base + 4];    ah[mt][3] = Qh[base + 8 * QSTR + 4];
                al[mt][0] = Ql[base];        al[mt][1] = Ql[base + 8 * QSTR];
                al[mt][2] = Ql[base + 4];    al[mt][3] = Ql[base + 8 * QSTR + 4];
            }
            #pragma unroll
            for (int nt = 0; nt < 8; nt++) {
                const int nb = (wc * 64 + nt * 8 + g) * WCSTR + ks * 8 + tig;
                u32 bh[2] = { Bh[nb], Bh[nb + 4] };
                u32 bl[2] = { Bl[nb], Bl[nb + 4] };
                #pragma unroll
                for (int mt = 0; mt < 2; mt++) {
                    mma16816(d[mt][nt], ah[mt], bh);
                    mma16816(d[mt][nt], ah[mt], bl);
                    mma16816(d[mt][nt], al[mt], bh);
                }
            }
        }
    }

    // ---- epilogue: + b_out + c @ U, direct float2 stores ----
    {
        const float* fc = f + 2816;
        #pragma unroll
        for (int mt = 0; mt < 2; mt++) {
            const int r0 = wr * 32 + mt * 16 + g;
            const int r1 = r0 + 8;
            float cc0[8], cc1[8];
            #pragma unroll
            for (int h = 0; h < 8; h++) { cc0[h] = fc[r0 * 8 + h]; cc1[h] = fc[r1 * 8 + h]; }
            #pragma unroll
            for (int nt = 0; nt < 8; nt++) {
                const int col = wc * 64 + nt * 8 + tig * 2;
                const float2 bo = *(const float2*)(f + 512 + col);
                float v00 = d[mt][nt][0] + bo.x;
                float v01 = d[mt][nt][1] + bo.y;
                float v10 = d[mt][nt][2] + bo.x;
                float v11 = d[mt][nt][3] + bo.y;
                #pragma unroll
                for (int h = 0; h < 8; h++) {
                    const float2 u2 = *(const float2*)(f + 768 + h * 256 + col);
                    v00 = fmaf(cc0[h], u2.x, v00);
                    v01 = fmaf(cc0[h], u2.y, v01);
                    v10 = fmaf(cc1[h], u2.x, v10);
                    v11 = fmaf(cc1[h], u2.y, v11);
                }
                float2* o0 = (float2*)(out + (size_t)(row0 + r0) * 256 + col);
                float2* o1 = (float2*)(out + (size_t)(row0 + r1) * 256 + col);
                *o0 = make_float2(v00, v01);
                *o1 = make_float2(v10, v11);
            }
        }
    }
}

// ---------------- launch ----------------------------------------------------
extern "C" void kernel_launch(void* const* d_in, const int* in_sizes, int n_in,
                              void* d_out, int out_size)
{
    const float* node    = (const float*)d_in[0];
    const float* energy  = (const float*)d_in[2];
    const float* W_node  = (const float*)d_in[3];
    const float* b_node  = (const float*)d_in[4];
    const float* W_graph = (const float*)d_in[7];
    const float* b_graph = (const float*)d_in[8];
    const float* Wq      = (const float*)d_in[9];
    const float* bq      = (const float*)d_in[10];
    const float* Wk      = (const float*)d_in[11];
    const float* bk      = (const float*)d_in[12];
    const float* Wv      = (const float*)d_in[13];
    const float* bv      = (const float*)d_in[14];
    const float* W_out   = (const float*)d_in[15];
    const float* b_out   = (const float*)d_in[16];
    float* out = (float*)d_out;

    p1_kernel<<<1, 256>>>(energy, W_graph, b_graph);
    p2_kernel<<<96, 256>>>(Wk, bk, Wv, bv, Wq, bq, b_node);
    p3_kernel<<<9, 256>>>(W_out);
    p4_kernel<<<128, 256>>>(W_node, Wq);
    p5_kernel<<<256, 256>>>(W_out);

    cudaFuncSetAttribute(ghca_main_kernel,
                         cudaFuncAttributeMaxDynamicSharedMemorySize, SMEM_BYTES);
    ghca_main_kernel<<<NBLKS, THREADS, SMEM_BYTES>>>(node, b_out, out);
}

// round 6
// speedup vs baseline: 5.2277x; 1.7589x over previous
#include <cuda_runtime.h>
#include <cuda_fp16.h>
#include <cstdint>

typedef uint32_t u32;

// Fixed dims: 65536 rows, Dn=128, L=256, H=8, DH=32. Only graph branch matters
// (reference loop overwrites `out`; graph branch has T=1 -> rank-1 kv).
#define NROWS_TOTAL 65536
#define ROWS_PER_BLK 128
#define THREADS 512
#define NBLKS (NROWS_TOTAL / ROWS_PER_BLK)   // 512

// ---------------- SMEM layout (bytes) --------------------------------------
// f[0..4095] floats: f[0..255] bnq | f[256..511] kvec | f[512..767] b_out
//                    f[768..2815] U[8][256] | f[2816..3839] c[128][8]
// phase1: X  @16384 (34816B, fp16 [128][136] pad)  WNQ @51200 (69632B [256][136])
// phase2: Q  @16384 (67584B, fp16 [128][264] pad)  WC  @83968 (36864B [256][72])
#define OFF_X    16384
#define OFF_WNQ  51200
#define OFF_Q    16384
#define OFF_WC   83968
#define SMEM_BYTES 120832

// row strides in u32 words (half pairs); stride%32==4 -> conflict-free frags
#define XSTR 68     // 128 half + 8 pad
#define QSTR 132    // 256 half + 8 pad
#define WCSTR 36    // 64 half + 8 pad

// ---------------- device globals (precomputed each launch) -----------------
__device__ float  g_p4part[4 * 128 * 256];    // K-split partials of W_node@Wq
__device__ __half g_Wnq[256 * 136];           // (W_node@Wq)^T [n][k] padded
__device__ __half g_Wout[256 * 264];          // W_out^T       [n][k] padded
__device__ float g_bnq[256], g_kvec[256], g_U[2048];
__device__ float g_kraw[256], g_vraw[256];

// ---------------- helpers ---------------------------------------------------
__device__ __forceinline__ void mma16816(float* d, const u32* a, const u32* b) {
    asm volatile(
        "mma.sync.aligned.m16n8k16.row.col.f32.f16.f16.f32 "
        "{%0,%1,%2,%3}, {%4,%5,%6,%7}, {%8,%9}, {%0,%1,%2,%3};"
        : "+f"(d[0]), "+f"(d[1]), "+f"(d[2]), "+f"(d[3])
        : "r"(a[0]), "r"(a[1]), "r"(a[2]), "r"(a[3]), "r"(b[0]), "r"(b[1]));
}
__device__ __forceinline__ u32 packh2(float x, float y) {
    __half2 h = __floats2half2_rn(x, y);
    return *reinterpret_cast<u32*>(&h);
}

// ---------------- precompute kernels ---------------------------------------
// p2: merged lifted-graph + three K=256 GEMVs, warp-per-output:
//   oid 0..255   : kraw[j] = bk2[j] + lg @ Wk2[:,j]
//   oid 256..511 : vraw[j] = bv2[j] + lg @ Wv2[:,j]
//   oid 512..767 : bnq[j]  = bq[j]  + b_node @ Wq[:,j]
__global__ void p2_kernel(const float* __restrict__ energy,
                          const float* __restrict__ W_graph,
                          const float* __restrict__ b_graph,
                          const float* __restrict__ Wk, const float* __restrict__ bk,
                          const float* __restrict__ Wv, const float* __restrict__ bv,
                          const float* __restrict__ Wq, const float* __restrict__ bq,
                          const float* __restrict__ b_node)
{
    __shared__ float lg[256];
    const int warp = threadIdx.x >> 5, lane = threadIdx.x & 31;
    const int oid = blockIdx.x * 8 + warp;
    const int kind = oid >> 8;
    const int j = oid & 255;

    // every block rebuilds lifted_graph locally (8K FLOP, removes p1 kernel)
    {
        const int t = threadIdx.x;
        float acc = b_graph[t];
        #pragma unroll
        for (int d = 0; d < 32; d++) acc += energy[d] * W_graph[d * 256 + t];
        lg[t] = acc;
    }
    __syncthreads();

    const float* W; const float* xv; float bias;
    if (kind == 0)      { W = Wk + 2 * 65536; xv = lg;     bias = bk[512 + j]; }
    else if (kind == 1) { W = Wv + 2 * 65536; xv = lg;     bias = bv[512 + j]; }
    else                { W = Wq;             xv = b_node; bias = bq[j]; }
    float s = 0.0f;
    #pragma unroll
    for (int u = 0; u < 8; u++) { int i = lane + 32 * u; s += xv[i] * W[i * 256 + j]; }
    #pragma unroll
    for (int o = 16; o > 0; o >>= 1) s += __shfl_xor_sync(0xffffffffu, s, o);
    if (lane == 0) {
        s += bias;
        if (kind == 0) g_kraw[j] = s;
        else if (kind == 1) g_vraw[j] = s;
        else g_bnq[j] = s;
    }
}

__global__ void p3_kernel(const float* __restrict__ W_out)
{
    const int j = threadIdx.x;
    if (blockIdx.x == 0) {
        const int w = j >> 5, lane = j & 31;
        float x = g_kraw[w * 32 + lane];
        float m = x;
        #pragma unroll
        for (int o = 16; o > 0; o >>= 1) m = fmaxf(m, __shfl_xor_sync(0xffffffffu, m, o));
        const float e = __expf(x - m);
        float s = e;
        #pragma unroll
        for (int o = 16; o > 0; o >>= 1) s += __shfl_xor_sync(0xffffffffu, s, o);
        g_kvec[w * 32 + lane] = e / s;
    } else {
        const int h = blockIdx.x - 1;
        __shared__ float sv[32];
        if (j < 32) sv[j] = g_vraw[h * 32 + j];
        __syncthreads();
        float u = 0.0f;
        #pragma unroll
        for (int e2 = 0; e2 < 32; e2++) u += sv[e2] * W_out[(h * 32 + e2) * 256 + j];
        g_U[h * 256 + j] = u;
    }
}

// p4: K-split partials of Wnq = W_node @ Wq. block = (i row, kc chunk of 64).
__global__ void p4_kernel(const float* __restrict__ W_node,
                          const float* __restrict__ Wq)
{
    __shared__ float wn[64];
    const int i = blockIdx.x, kc = blockIdx.y;
    const int j = threadIdx.x;
    if (j < 64) wn[j] = W_node[i * 256 + kc * 64 + j];
    __syncthreads();
    const float* Wqp = Wq + (kc * 64) * 256 + j;
    float a0 = 0.f, a1 = 0.f, a2 = 0.f, a3 = 0.f;
    #pragma unroll
    for (int m = 0; m < 64; m += 4) {
        a0 = fmaf(wn[m],     Wqp[m * 256],       a0);
        a1 = fmaf(wn[m + 1], Wqp[(m + 1) * 256], a1);
        a2 = fmaf(wn[m + 2], Wqp[(m + 2) * 256], a2);
        a3 = fmaf(wn[m + 3], Wqp[(m + 3) * 256], a3);
    }
    g_p4part[(kc * 128 + i) * 256 + j] = (a0 + a1) + (a2 + a3);
}

// p6: reduce partials, convert fp16, store transposed+padded.
__global__ void p6_kernel()
{
    const int j = blockIdx.x;    // n 0..255
    const int i = threadIdx.x;   // k 0..127
    float s = g_p4part[i * 256 + j] + g_p4part[(128 + i) * 256 + j]
            + g_p4part[(256 + i) * 256 + j] + g_p4part[(384 + i) * 256 + j];
    g_Wnq[j * 136 + i] = __float2half(s);
}

// p5: W_out -> fp16 transposed+padded.
__global__ void p5_kernel(const float* __restrict__ W_out)
{
    const int m = blockIdx.x;    // k 0..255
    const int j = threadIdx.x;   // n 0..255
    g_Wout[j * 264 + m] = __float2half(W_out[m * 256 + j]);
}

// ---------------- main HMMA kernel -----------------------------------------
extern __shared__ char s_raw[];

__global__ __launch_bounds__(THREADS, 1)
void ghca_main_kernel(const float* __restrict__ X,
                      const float* __restrict__ b_out,
                      float* __restrict__ out)
{
    float* f = (float*)s_raw;
    const int tid = threadIdx.x;
    const int wid = tid >> 5, lane = tid & 31;
    const int g = lane >> 2, tig = lane & 3;
    const int wr = wid & 3, wc = wid >> 2;     // warp: rows wr*32.., cols wc*64..
    const int row0 = blockIdx.x * ROWS_PER_BLK;

    // ---- stage small arrays ----
    for (int t = tid; t < 256; t += THREADS) {
        f[t]       = g_bnq[t];
        f[256 + t] = g_kvec[t];
        f[512 + t] = b_out[t];
    }
    for (int t = tid; t < 2048; t += THREADS) f[768 + t] = g_U[t];

    // ---- stage X fp16 (row-major padded) ----
    {
        u32* xh = (u32*)(s_raw + OFF_X);
        const float2* xs = (const float2*)(X + (size_t)row0 * 128);
        #pragma unroll 4
        for (int idx = tid; idx < 8192; idx += THREADS) {
            const int r = idx >> 6, cp = idx & 63;
            float2 v = xs[idx];
            xh[r * XSTR + cp] = packh2(v.x, v.y);
        }
    }
    // ---- stage Wnq (linear copy, array already padded) ----
    {
        float4* dh = (float4*)(s_raw + OFF_WNQ);
        const float4* sh = (const float4*)g_Wnq;
        #pragma unroll 4
        for (int t = tid; t < 4352; t += THREADS) dh[t] = sh[t];
    }
    __syncthreads();

    float d[2][8][4];
    #pragma unroll
    for (int mt = 0; mt < 2; mt++)
        #pragma unroll
        for (int nt = 0; nt < 8; nt++)
            #pragma unroll
            for (int c = 0; c < 4; c++) d[mt][nt][c] = 0.0f;

    // ---- phase 1: Y = X @ Wnq  (K=128, 8 ksteps) ----
    {
        const u32* Xh = (const u32*)(s_raw + OFF_X);
        const u32* Bh = (const u32*)(s_raw + OFF_WNQ);
        #pragma unroll
        for (int ks = 0; ks < 8; ks++) {
            u32 ah[2][4];
            #pragma unroll
            for (int mt = 0; mt < 2; mt++) {
                const int base = (wr * 32 + mt * 16 + g) * XSTR + ks * 8 + tig;
                ah[mt][0] = Xh[base];     ah[mt][1] = Xh[base + 8 * XSTR];
                ah[mt][2] = Xh[base + 4]; ah[mt][3] = Xh[base + 8 * XSTR + 4];
            }
            #pragma unroll
            for (int nt = 0; nt < 8; nt++) {
                const int nb = (wc * 64 + nt * 8 + g) * XSTR + ks * 8 + tig;
                u32 bh[2] = { Bh[nb], Bh[nb + 4] };
                #pragma unroll
                for (int mt = 0; mt < 2; mt++) mma16816(d[mt][nt], ah[mt], bh);
            }
        }
    }
    __syncthreads();   // phase1 SMEM reads done; safe to overwrite with Q

    // ---- softmax per row per head, build c, write Q fp16 to SMEM ----
    {
        u32* Qh = (u32*)(s_raw + OFF_Q);
        float* fc = f + 2816;
        #pragma unroll
        for (int mt = 0; mt < 2; mt++) {
            #pragma unroll
            for (int rh = 0; rh < 2; rh++) {
                const int row = wr * 32 + mt * 16 + rh * 8 + g;
                #pragma unroll
                for (int hg = 0; hg < 2; hg++) {
                    const int head = wc * 2 + hg;
                    float y[8];
                    #pragma unroll
                    for (int q = 0; q < 4; q++) {
                        const int col = wc * 64 + (hg * 4 + q) * 8 + tig * 2;
                        y[q * 2]     = d[mt][hg * 4 + q][rh * 2]     + f[col];
                        y[q * 2 + 1] = d[mt][hg * 4 + q][rh * 2 + 1] + f[col + 1];
                    }
                    float mx = y[0];
                    #pragma unroll
                    for (int q = 1; q < 8; q++) mx = fmaxf(mx, y[q]);
                    mx = fmaxf(mx, __shfl_xor_sync(0xffffffffu, mx, 1));
                    mx = fmaxf(mx, __shfl_xor_sync(0xffffffffu, mx, 2));
                    float s = 0.0f;
                    #pragma unroll
                    for (int q = 0; q < 8; q++) { y[q] = __expf(y[q] - mx); s += y[q]; }
                    s += __shfl_xor_sync(0xffffffffu, s, 1);
                    s += __shfl_xor_sync(0xffffffffu, s, 2);
                    const float inv = 1.0f / s;
                    float pd = 0.0f;
                    #pragma unroll
                    for (int q = 0; q < 4; q++) {
                        const int col = wc * 64 + (hg * 4 + q) * 8 + tig * 2;
                        y[q * 2]     *= inv;
                        y[q * 2 + 1] *= inv;
                        pd += y[q * 2] * f[256 + col] + y[q * 2 + 1] * f[256 + col + 1];
                    }
                    pd += __shfl_xor_sync(0xffffffffu, pd, 1);
                    pd += __shfl_xor_sync(0xffffffffu, pd, 2);
                    if (tig == 0)
                        fc[row * 8 + head] = (pd >= 1e-8f) ? 1.0f : pd * 1e8f;
                    #pragma unroll
                    for (int q = 0; q < 4; q++) {
                        const int wi = row * QSTR + wc * 32 + (hg * 4 + q) * 4 + tig;
                        Qh[wi] = packh2(y[q * 2], y[q * 2 + 1]);
                    }
                }
            }
        }
    }

    // ---- phase 2: Z = Q @ W_out  (K=256, 4 staged chunks of 64) ----
    #pragma unroll
    for (int mt = 0; mt < 2; mt++)
        #pragma unroll
        for (int nt = 0; nt < 8; nt++)
            #pragma unroll
            for (int c = 0; c < 4; c++) d[mt][nt][c] = 0.0f;

    for (int ck = 0; ck < 4; ck++) {
        __syncthreads();   // previous chunk reads (or Q writes) complete
        {
            float4* dh = (float4*)(s_raw + OFF_WC);
            const float4* sh = (const float4*)g_Wout;
            #pragma unroll
            for (int t = tid; t < 2048; t += THREADS) {
                const int r = t >> 3, seg = t & 7;
                dh[r * 9 + seg] = sh[r * 33 + ck * 8 + seg];  // 264 half = 33 f4
            }
        }
        __syncthreads();
        const u32* Qh = (const u32*)(s_raw + OFF_Q);
        const u32* Bh = (const u32*)(s_raw + OFF_WC);
        #pragma unroll
        for (int ks = 0; ks < 4; ks++) {
            u32 ah[2][4];
            #pragma unroll
            for (int mt = 0; mt < 2; mt++) {
                const int base = (wr * 32 + mt * 16 + g) * QSTR + ck * 32 + ks * 8 + tig;
                ah[mt][0] = Qh[base];     ah[mt][1] = Qh[base + 8 * QSTR];
                ah[mt][2] = Qh[base + 4]; ah[mt][3] = Qh[base + 8 * QSTR + 4];
            }
            #pragma unroll
            for (int nt = 0; nt < 8; nt++) {
                const int nb = (wc * 64 + nt * 8 + g) * WCSTR + ks * 8 + tig;
                u32 bh[2] = { Bh[nb], Bh[nb + 4] };
                #pragma unroll
                for (int mt = 0; mt < 2; mt++) mma16816(d[mt][nt], ah[mt], bh);
            }
        }
    }

    // ---- epilogue: + b_out + c @ U, direct float2 stores ----
    {
        const float* fc = f + 2816;
        #pragma unroll
        for (int mt = 0; mt < 2; mt++) {
            const int r0 = wr * 32 + mt * 16 + g;
            const int r1 = r0 + 8;
            float cc0[8], cc1[8];
            #pragma unroll
            for (int h = 0; h < 8; h++) { cc0[h] = fc[r0 * 8 + h]; cc1[h] = fc[r1 * 8 + h]; }
            #pragma unroll
            for (int nt = 0; nt < 8; nt++) {
                const int col = wc * 64 + nt * 8 + tig * 2;
                const float2 bo = *(const float2*)(f + 512 + col);
                float v00 = d[mt][nt][0] + bo.x;
                float v01 = d[mt][nt][1] + bo.y;
                float v10 = d[mt][nt][2] + bo.x;
                float v11 = d[mt][nt][3] + bo.y;
                #pragma unroll
                for (int h = 0; h < 8; h++) {
                    const float2 u2 = *(const float2*)(f + 768 + h * 256 + col);
                    v00 = fmaf(cc0[h], u2.x, v00);
                    v01 = fmaf(cc0[h], u2.y, v01);
                    v10 = fmaf(cc1[h], u2.x, v10);
                    v11 = fmaf(cc1[h], u2.y, v11);
                }
                float2* o0 = (float2*)(out + (size_t)(row0 + r0) * 256 + col);
                float2* o1 = (float2*)(out + (size_t)(row0 + r1) * 256 + col);
                *o0 = make_float2(v00, v01);
                *o1 = make_float2(v10, v11);
            }
        }
    }
}

// ---------------- launch ----------------------------------------------------
extern "C" void kernel_launch(void* const* d_in, const int* in_sizes, int n_in,
                              void* d_out, int out_size)
{
    const float* node    = (const float*)d_in[0];
    const float* energy  = (const float*)d_in[2];
    const float* W_node  = (const float*)d_in[3];
    const float* b_node  = (const float*)d_in[4];
    const float* W_graph = (const float*)d_in[7];
    const float* b_graph = (const float*)d_in[8];
    const float* Wq      = (const float*)d_in[9];
    const float* bq      = (const float*)d_in[10];
    const float* Wk      = (const float*)d_in[11];
    const float* bk      = (const float*)d_in[12];
    const float* Wv      = (const float*)d_in[13];
    const float* bv      = (const float*)d_in[14];
    const float* W_out   = (const float*)d_in[15];
    const float* b_out   = (const float*)d_in[16];
    float* out = (float*)d_out;

    p2_kernel<<<96, 256>>>(energy, W_graph, b_graph, Wk, bk, Wv, bv, Wq, bq, b_node);
    p3_kernel<<<9, 256>>>(W_out);
    p4_kernel<<<dim3(128, 4), 256>>>(W_node, Wq);
    p5_kernel<<<256, 256>>>(W_out);
    p6_kernel<<<256, 128>>>();

    cudaFuncSetAttribute(ghca_main_kernel,
                         cudaFuncAttributeMaxDynamicSharedMemorySize, SMEM_BYTES);
    ghca_main_kernel<<<NBLKS, THREADS, SMEM_BYTES>>>(node, b_out, out);
}